// round 17
// baseline (speedup 1.0000x reference)
#include <cuda_runtime.h>
#include <cuda_fp16.h>
#include <cstdint>
#include <math.h>

#define N_    8192
#define D_    256
#define NPID  256
#define NB    64
#define TT    2080
#define NCTA  148
#define FIXS  1099511627776.f   // 2^40

__device__ float    g_normed[N_ * D_];
// pre-swizzled fp16: [block(64KB)][kchunk(16KB)][row(128B)][16B-unit ^ (row&7)]
__device__ __align__(16) __half g_swz[N_ * D_];
__device__ float    g_hp[N_];
__device__ float    g_validf[N_];
__device__ int      g_colsent[N_];
__device__ unsigned g_aE[N_];
__device__ unsigned g_bE[N_];
__device__ unsigned long long g_sumFx;
__device__ unsigned long long g_cntI;
__device__ unsigned g_done;
__device__ unsigned g_hprdy;

__device__ __forceinline__ unsigned encf(float f) {
    unsigned u = __float_as_uint(f);
    return (u & 0x80000000u) ? ~u : (u | 0x80000000u);
}
__device__ __forceinline__ float decf(unsigned e) {
    unsigned u = (e & 0x80000000u) ? (e ^ 0x80000000u) : ~e;
    return __uint_as_float(u);
}
__device__ __forceinline__ uint32_t smem_u32(const void* p) {
    uint32_t a;
    asm("{ .reg .u64 t; cvta.to.shared.u64 t, %1; cvt.u32.u64 %0, t; }" : "=r"(a) : "l"(p));
    return a;
}
__device__ __forceinline__ void cpa16(uint32_t d, const void* s) {
    asm volatile("cp.async.cg.shared.global [%0], [%1], 16;" :: "r"(d), "l"(s) : "memory");
}
__device__ __forceinline__ void cpa_mbar(uint32_t b) {
    asm volatile("cp.async.mbarrier.arrive.noinc.shared.b64 [%0];" :: "r"(b) : "memory");
}
__device__ __forceinline__ void bar_init(uint32_t b, uint32_t c) {
    asm volatile("mbarrier.init.shared.b64 [%0], %1;" :: "r"(b), "r"(c) : "memory");
}
__device__ __forceinline__ void bar_arrive(uint32_t b) {
    asm volatile("mbarrier.arrive.shared.b64 _, [%0];" :: "r"(b) : "memory");
}
__device__ __forceinline__ void bar_wait(uint32_t b, uint32_t ph) {
    asm volatile("{\n\t.reg .pred P;\n\tWL%=:\n\t"
                 "mbarrier.try_wait.parity.acquire.cta.shared::cta.b64 P, [%0], %1, 0x989680;\n\t"
                 "@P bra.uni WD%=;\n\tbra.uni WL%=;\n\tWD%=:\n\t}" :: "r"(b), "r"(ph) : "memory");
}
__device__ __forceinline__ void ldsm4(uint32_t& r0, uint32_t& r1, uint32_t& r2, uint32_t& r3,
                                      uint32_t addr) {
    asm volatile("ldmatrix.sync.aligned.m8n8.x4.shared.b16 {%0,%1,%2,%3}, [%4];"
                 : "=r"(r0), "=r"(r1), "=r"(r2), "=r"(r3) : "r"(addr));
}
__device__ __forceinline__ void mma16816(float& c0, float& c1, float& c2, float& c3,
                                         uint32_t a0, uint32_t a1, uint32_t a2, uint32_t a3,
                                         uint32_t b0, uint32_t b1) {
    asm volatile("mma.sync.aligned.m16n8k16.row.col.f32.f16.f16.f32 "
                 "{%0,%1,%2,%3},{%4,%5,%6,%7},{%8,%9},{%0,%1,%2,%3};"
                 : "+f"(c0), "+f"(c1), "+f"(c2), "+f"(c3)
                 : "r"(a0), "r"(a1), "r"(a2), "r"(a3), "r"(b0), "r"(b1));
}
__device__ __forceinline__ void dec_tri(int k, int& bi, int& bj) {
    int b = (int)((sqrtf(8.f * (float)k + 1.f) - 1.f) * 0.5f);
    while ((b + 1) * (b + 2) / 2 <= k) b++;
    while (b * (b + 1) / 2 > k) b--;
    bi = b;
    bj = k - b * (b + 1) / 2;
}

// ---------------- normalize: one warp per row, no smem/barriers ----------------
__global__ void normalize_k(const float* __restrict__ emb,
                            const int* __restrict__ labels,
                            const int* __restrict__ pids) {
    int lane = threadIdx.x & 31, w = threadIdx.x >> 5;
    int j = blockIdx.x * 8 + w;
    const float4* src = (const float4*)(emb + (size_t)j * D_);
    float4 v0 = src[lane];
    float4 v1 = src[lane + 32];
    float ss = v0.x * v0.x + v0.y * v0.y + v0.z * v0.z + v0.w * v0.w +
               v1.x * v1.x + v1.y * v1.y + v1.z * v1.z + v1.w * v1.w;
    for (int o = 16; o; o >>= 1) ss += __shfl_xor_sync(0xffffffffu, ss, o);
    float inv = 1.0f / fmaxf(sqrtf(ss), 1e-12f);
    float4 o0 = make_float4(v0.x * inv, v0.y * inv, v0.z * inv, v0.w * inv);
    float4 o1 = make_float4(v1.x * inv, v1.y * inv, v1.z * inv, v1.w * inv);
    float4* dstf = (float4*)(g_normed + (size_t)j * D_);
    dstf[lane] = o0;
    dstf[lane + 32] = o1;
    int b = j >> 7, r = j & 127;
    char* base = (char*)g_swz + (size_t)b * 65536 + r * 128;
#pragma unroll
    for (int p = 0; p < 2; p++) {
        float4 ov = p ? o1 : o0;
        int f = lane + p * 32;
        int c16 = f >> 1, q = c16 >> 3, u = c16 & 7;
        char* dst = base + q * 16384 + ((u ^ (r & 7)) << 4) + (f & 1) * 8;
        *(__half2*)dst = __floats2half2_rn(ov.x, ov.y);
        *(__half2*)(dst + 4) = __floats2half2_rn(ov.z, ov.w);
    }
    if (lane == 0) {
        g_hp[j] = 1e9f;
        g_validf[j] = 0.f;
        unsigned e = encf(-1e9f);
        g_aE[j] = e;
        g_bE[j] = e;
        g_colsent[j] = (labels[j] == 1) ? pids[j] : -1;
        if (j == 0) { g_sumFx = 0ull; g_cntI = 0ull; g_done = 0u; g_hprdy = 0u; }
    }
}

// ---- main: inlined hp prepass + triangular GEMM + 4x32KB mbarrier ring ----
__global__ void __launch_bounds__(512, 1)
main_k(const int* __restrict__ pids, const int* __restrict__ labels) {
    extern __shared__ char sm[];
    uint32_t sb = smem_u32(sm);
    const uint32_t A0 = sb, BST = sb + 65536;   // A 64K, B ring 4x32K
    __shared__ __align__(8) unsigned long long s_bar[9];
    __shared__ int s_list[1024];
    __shared__ int s_n;
    uint32_t bar = smem_u32(s_bar);
#define FULLB(s) (bar + (s) * 8)
#define EMPTB(s) (bar + 32 + (s) * 8)
#define ABAR     (bar + 64)

    int tid = threadIdx.x, lane = tid & 31, wid = tid >> 5;
    int wr = (wid >> 2) * 32;
    int wc = (wid & 3) * 32;
    int gid = lane >> 2, tig = lane & 3;

    // ================= inlined hardest-positive (2 pids per CTA) =================
    {
        float* srow = (float*)sm;   // 64 rows x 256 floats (reused as A later)
        for (int pp = 0; pp < 2; pp++) {
            int p = blockIdx.x + pp * NCTA;
            if (p < NPID) {
                if (tid == 0) s_n = 0;
                __syncthreads();
                for (int j = tid; j < N_; j += 512)
                    if (pids[j] == p && labels[j] == 1) {
                        int q = atomicAdd(&s_n, 1);
                        if (q < 1024) s_list[q] = j;
                    }
                __syncthreads();
                int n = s_n < 1024 ? s_n : 1024;
                if (n > 0) {
                    int ns = (n < 64) ? n : 64;
                    for (int idx = tid; idx < ns * 64; idx += 512) {
                        int m = idx >> 6, q = idx & 63;
                        ((float4*)srow)[m * 64 + q] =
                            ((const float4*)(g_normed + (size_t)s_list[m] * D_))[q];
                    }
                    __syncthreads();
                    float vf = (n >= 2) ? 1.f : 0.f;
                    for (int a = wid; a < n; a += 16) {
                        int i = s_list[a];
                        const float* arow = (a < ns) ? (srow + a * D_)
                                                     : (g_normed + (size_t)i * D_);
                        float a8[8];
#pragma unroll
                        for (int k = 0; k < 8; k++) a8[k] = arow[k * 32 + lane];
                        float hp = 1e9f;
                        for (int j2 = 0; j2 < n; j2++) {
                            if (j2 == a) continue;
                            const float* br = (j2 < ns) ? (srow + j2 * D_)
                                                        : (g_normed + (size_t)s_list[j2] * D_);
                            float s = 0.f;
#pragma unroll
                            for (int k = 0; k < 8; k++)
                                s = fmaf(a8[k], br[k * 32 + lane], s);
                            for (int o = 16; o; o >>= 1)
                                s += __shfl_xor_sync(0xffffffffu, s, o);
                            hp = fminf(hp, s);
                        }
                        if (lane == 0) { g_hp[i] = hp; g_validf[i] = vf; }
                    }
                }
                __syncthreads();    // done with srow/s_list before next pid / A load
            }
        }
        __threadfence();            // publish this CTA's g_hp/g_validf stores
        __syncthreads();
        if (tid == 0) atomicAdd(&g_hprdy, 1u);
    }

    // ================= GEMM =================
    int k0 = (int)(((long long)blockIdx.x * TT) / NCTA);
    int k1 = (int)(((long long)(blockIdx.x + 1) * TT) / NCTA);
    if (k0 >= k1) return;
    int nch = (k1 - k0) * 2;     // 2 x 32KB chunks per tile

    if (tid == 0) {
        for (int s = 0; s < 4; s++) { bar_init(FULLB(s), 512); bar_init(EMPTB(s), 512); }
        bar_init(ABAR, 512);
    }
    __syncthreads();

    int bi0, bj0;
    dec_tri(k0, bi0, bj0);

    // prologue: A(bi0) + first 2 chunks — issued BEFORE the hp spin so the
    // loads fly while we wait for other CTAs' hp results.
    {
        const char* asrc = (const char*)g_swz + (size_t)bi0 * 65536;
#pragma unroll
        for (int i = 0; i < 8; i++)
            cpa16(A0 + i * 8192 + tid * 16, asrc + i * 8192 + tid * 16);
        cpa_mbar(ABAR);
    }
    int nbi = bi0, nbj = bj0;
    int npro = nch < 2 ? nch : 2;
    for (int g = 0; g < npro; g++) {
        const char* src = (const char*)g_swz + (size_t)nbj * 65536 + (size_t)(g & 1) * 32768;
#pragma unroll
        for (int i = 0; i < 4; i++)
            cpa16(BST + g * 32768 + i * 8192 + tid * 16, src + i * 8192 + tid * 16);
        cpa_mbar(FULLB(g));
    }

    // wait for ALL CTAs' hp (all 148 CTAs are co-resident: no deadlock)
    if (tid == 0) {
        while (*(volatile unsigned*)&g_hprdy < NCTA) __nanosleep(64);
    }
    __syncthreads();
    __threadfence();

    int ar = 0;
    bar_wait(ABAR, 0);

    float hp_s[4], mA[4], mB[4];
    int pid_s[4], rsent[4];
    int cur_bi = bi0;
#pragma unroll
    for (int m = 0; m < 2; m++) {
        int rA = bi0 * 128 + wr + m * 16 + gid;
        hp_s[2 * m] = g_hp[rA];         pid_s[2 * m] = pids[rA];     rsent[2 * m] = g_colsent[rA];
        hp_s[2 * m + 1] = g_hp[rA + 8]; pid_s[2 * m + 1] = pids[rA + 8]; rsent[2 * m + 1] = g_colsent[rA + 8];
    }
#pragma unroll
    for (int s = 0; s < 4; s++) { mA[s] = -1e9f; mB[s] = -1e9f; }

    int arow = lane & 15;
    int kha = lane >> 4;
    int brow = ((lane >> 4) & 1) * 8 + (lane & 7);
    int khb = (lane >> 3) & 1;
    int xr = lane & 7;

    int bi = bi0, bj = bj0;
    for (int t = k0; t < k1; t++) {
        if (bi != cur_bi) {
#pragma unroll
            for (int s = 0; s < 4; s++) {
                float a = mA[s], b = mB[s];
                for (int o = 1; o < 4; o <<= 1) {
                    a = fmaxf(a, __shfl_xor_sync(0xffffffffu, a, o));
                    b = fmaxf(b, __shfl_xor_sync(0xffffffffu, b, o));
                }
                if (tig == 0) {
                    int r = cur_bi * 128 + wr + (s >> 1) * 16 + (s & 1) * 8 + gid;
                    atomicMax(&g_aE[r], encf(a));
                    atomicMax(&g_bE[r], encf(b));
                }
                mA[s] = -1e9f; mB[s] = -1e9f;
            }
            __syncthreads();   // all warps done reading old A
            const char* asrc = (const char*)g_swz + (size_t)bi * 65536;
#pragma unroll
            for (int i = 0; i < 8; i++)
                cpa16(A0 + i * 8192 + tid * 16, asrc + i * 8192 + tid * 16);
            cpa_mbar(ABAR);
            ar++;
            bar_wait(ABAR, ar & 1);
#pragma unroll
            for (int m = 0; m < 2; m++) {
                int rA = bi * 128 + wr + m * 16 + gid;
                hp_s[2 * m] = g_hp[rA];         pid_s[2 * m] = pids[rA];     rsent[2 * m] = g_colsent[rA];
                hp_s[2 * m + 1] = g_hp[rA + 8]; pid_s[2 * m + 1] = pids[rA + 8]; rsent[2 * m + 1] = g_colsent[rA + 8];
            }
            cur_bi = bi;
        }

        bool offdiag = (bi != bj);
        int cbase = bj * 128 + wc;
        int sv[4][2], pidc[4][2];
        float hpc[4][2];
#pragma unroll
        for (int n = 0; n < 4; n++) {
#pragma unroll
            for (int c = 0; c < 2; c++) {
                int cg = cbase + n * 8 + tig * 2 + c;
                sv[n][c] = __ldg(&g_colsent[cg]);
                if (offdiag) {
                    pidc[n][c] = __ldg(&pids[cg]);
                    hpc[n][c] = __ldg(&g_hp[cg]);
                }
            }
        }

        float acc[2][4][4];
#pragma unroll
        for (int m = 0; m < 2; m++)
#pragma unroll
            for (int n = 0; n < 4; n++)
#pragma unroll
                for (int q = 0; q < 4; q++) acc[m][n][q] = 0.f;

        int gbase = (t - k0) * 2;
#pragma unroll
        for (int h = 0; h < 2; h++) {
            int g = gbase + h, s = g & 3;
            bar_wait(FULLB(s), (g >> 2) & 1);
#pragma unroll
            for (int qq = 0; qq < 2; qq++) {
                int q = h * 2 + qq;
                uint32_t Bs = BST + s * 32768 + qq * 16384;
                uint32_t bAddr0 = Bs + (wc + brow) * 128;
                uint32_t bAddr1 = Bs + (wc + 16 + brow) * 128;
                uint32_t aBase = A0 + q * 16384;
#pragma unroll
                for (int l = 0; l < 4; l++) {
                    uint32_t aoff = (uint32_t)(((l * 2 + kha) ^ xr) << 4);
                    uint32_t boff = (uint32_t)(((l * 2 + khb) ^ xr) << 4);
                    uint32_t a[2][4], b[2][4];
#pragma unroll
                    for (int m = 0; m < 2; m++)
                        ldsm4(a[m][0], a[m][1], a[m][2], a[m][3],
                              aBase + (wr + m * 16 + arow) * 128 + aoff);
                    ldsm4(b[0][0], b[0][1], b[0][2], b[0][3], bAddr0 + boff);
                    ldsm4(b[1][0], b[1][1], b[1][2], b[1][3], bAddr1 + boff);
#pragma unroll
                    for (int m = 0; m < 2; m++) {
                        mma16816(acc[m][0][0], acc[m][0][1], acc[m][0][2], acc[m][0][3],
                                 a[m][0], a[m][1], a[m][2], a[m][3], b[0][0], b[0][1]);
                        mma16816(acc[m][1][0], acc[m][1][1], acc[m][1][2], acc[m][1][3],
                                 a[m][0], a[m][1], a[m][2], a[m][3], b[0][2], b[0][3]);
                        mma16816(acc[m][2][0], acc[m][2][1], acc[m][2][2], acc[m][2][3],
                                 a[m][0], a[m][1], a[m][2], a[m][3], b[1][0], b[1][1]);
                        mma16816(acc[m][3][0], acc[m][3][1], acc[m][3][2], acc[m][3][3],
                                 a[m][0], a[m][1], a[m][2], a[m][3], b[1][2], b[1][3]);
                    }
                }
            }
            bar_arrive(EMPTB(s));

            int g2 = g + 2;
            if (g2 < nch) {
                int s2 = g2 & 3;
                if (g2 >= 4) bar_wait(EMPTB(s2), ((g2 - 4) >> 2) & 1);
                if ((g2 & 1) == 0) { nbj++; if (nbj > nbi) { nbi++; nbj = 0; } }
                const char* src = (const char*)g_swz + (size_t)nbj * 65536 +
                                  (size_t)(g2 & 1) * 32768;
#pragma unroll
                for (int i = 0; i < 4; i++)
                    cpa16(BST + s2 * 32768 + i * 8192 + tid * 16, src + i * 8192 + tid * 16);
                cpa_mbar(FULLB(s2));
            }
        }

        // row-anchor fold
#pragma unroll
        for (int n = 0; n < 4; n++) {
#pragma unroll
            for (int m = 0; m < 2; m++) {
#pragma unroll
                for (int h = 0; h < 2; h++) {
                    int slot = 2 * m + h;
                    float hpv = hp_s[slot];
                    int mp = pid_s[slot];
                    float v0 = acc[m][n][h * 2 + 0];
                    float v1 = acc[m][n][h * 2 + 1];
                    bool c0k = (sv[n][0] == mp), c1k = (sv[n][1] == mp);
                    float a0 = c0k ? -1e9f : v0;
                    float a1 = c1k ? -1e9f : v1;
                    mA[slot] = fmaxf(mA[slot], fmaxf(a0, a1));
                    float b0 = (c0k || v0 >= hpv) ? -1e9f : v0;
                    float b1 = (c1k || v1 >= hpv) ? -1e9f : v1;
                    mB[slot] = fmaxf(mB[slot], fmaxf(b0, b1));
                }
            }
        }

        // column-anchor fold (skip diagonal: row fold covers it)
        if (offdiag) {
#pragma unroll
            for (int n = 0; n < 4; n++) {
#pragma unroll
                for (int c = 0; c < 2; c++) {
                    int pj = pidc[n][c];
                    float hpj = hpc[n][c];
                    float cA = -1e9f, cB = -1e9f;
#pragma unroll
                    for (int m = 0; m < 2; m++) {
#pragma unroll
                        for (int h = 0; h < 2; h++) {
                            float v = acc[m][n][h * 2 + c];
                            bool kill = (rsent[2 * m + h] == pj);
                            cA = fmaxf(cA, kill ? -1e9f : v);
                            cB = fmaxf(cB, (kill || v >= hpj) ? -1e9f : v);
                        }
                    }
                    for (int o = 4; o < 32; o <<= 1) {
                        cA = fmaxf(cA, __shfl_xor_sync(0xffffffffu, cA, o));
                        cB = fmaxf(cB, __shfl_xor_sync(0xffffffffu, cB, o));
                    }
                    if (gid == 0) {
                        int cg = cbase + n * 8 + tig * 2 + c;
                        atomicMax(&g_aE[cg], encf(cA));
                        atomicMax(&g_bE[cg], encf(cB));
                    }
                }
            }
        }

        bj++;
        if (bj > bi) { bi++; bj = 0; }
    }

    // final flush
#pragma unroll
    for (int s = 0; s < 4; s++) {
        float a = mA[s], b = mB[s];
        for (int o = 1; o < 4; o <<= 1) {
            a = fmaxf(a, __shfl_xor_sync(0xffffffffu, a, o));
            b = fmaxf(b, __shfl_xor_sync(0xffffffffu, b, o));
        }
        if (tig == 0) {
            int r = cur_bi * 128 + wr + (s >> 1) * 16 + (s & 1) * 8 + gid;
            atomicMax(&g_aE[r], encf(a));
            atomicMax(&g_bE[r], encf(b));
        }
    }
#undef FULLB
#undef EMPTB
#undef ABAR
}

// ---------------- finish: partial reduce + last-block writeout ----------------
__global__ void finish_k(float* __restrict__ out) {
    int i = blockIdx.x * 256 + threadIdx.x;
    float loss = 0.f;
    int vcnt = 0;
    if (g_validf[i] > 0.f) {
        float hp = g_hp[i];
        float maxA = decf(g_aE[i]);
        float maxB = decf(g_bE[i]);
        float hn = (maxB > hp - 0.5f) ? maxB : maxA;
        float base = fmaxf(hn - hp + 0.5f, 0.f);
        float w = (hp < 0.6f || hn > 0.3f) ? 2.0f : 1.0f;
        loss = base * w + 0.5f * (1.0f - hp) + 0.5f * fmaxf(hn + 0.2f, 0.f);
        vcnt = 1;
    }
    unsigned long long fx = (unsigned long long)__float2ull_rn(loss * FIXS);
    for (int o = 16; o; o >>= 1) {
        fx += __shfl_xor_sync(0xffffffffu, fx, o);
        vcnt += __shfl_xor_sync(0xffffffffu, vcnt, o);
    }
    __shared__ unsigned long long sfx[8];
    __shared__ int scnt[8];
    int wid = threadIdx.x >> 5, lane = threadIdx.x & 31;
    if (lane == 0) { sfx[wid] = fx; scnt[wid] = vcnt; }
    __syncthreads();
    if (wid == 0 && lane == 0) {
        unsigned long long v = 0ull;
        int cc = 0;
        for (int q = 0; q < 8; q++) { v += sfx[q]; cc += scnt[q]; }
        atomicAdd(&g_sumFx, v);
        atomicAdd(&g_cntI, (unsigned long long)cc);
        __threadfence();
        unsigned tk = atomicAdd(&g_done, 1u);
        if (tk == gridDim.x - 1) {
            __threadfence();
            unsigned long long s = g_sumFx, c = g_cntI;
            out[0] = (c > 0ull) ? (float)((double)s / (double)FIXS / (double)c) : 0.f;
        }
    }
}

// ---------------- launcher ----------------
extern "C" void kernel_launch(void* const* d_in, const int* in_sizes, int n_in,
                              void* d_out, int out_size) {
    const float* emb = (const float*)d_in[0];
    const int* labels = (const int*)d_in[1];
    const int* pids = (const int*)d_in[2];
    float* out = (float*)d_out;

    cudaFuncSetAttribute(main_k, cudaFuncAttributeMaxDynamicSharedMemorySize, 196608);

    normalize_k<<<N_ / 8, 256>>>(emb, labels, pids);
    main_k<<<NCTA, 512, 196608>>>(pids, labels);
    finish_k<<<N_ / 256, 256>>>(out);
}